// round 1
// baseline (speedup 1.0000x reference)
#include <cuda_runtime.h>
#include <cuda_bf16.h>
#include <math.h>

// ---------------------------------------------------------------------------
// ConvNet: conv(3->16,5x5) -> hermite -> pool2 -> conv(16->16,5x5) -> hermite
//          -> pool2 -> FC(2704->10)
// B=512, input 3x64x64.
// ---------------------------------------------------------------------------

#define B_IMG 512

// Intermediate scratch (allocation-free rule: __device__ globals)
__device__ float g_pool1[B_IMG * 16 * 30 * 30];   // after conv1+herm+pool
__device__ float g_pool2[B_IMG * 16 * 13 * 13];   // after conv2+herm+pool

__device__ __forceinline__ float herm4(float x, float a0, float a1, float a2,
                                       float a3, float a4) {
    // degree-4 polynomial via Horner (monomial expansion of Hermite series)
    return fmaf(fmaf(fmaf(fmaf(a4, x, a3), x, a2), x, a1), x, a0);
}

// ---------------------------------------------------------------------------
// Kernel 1: conv1 + bias + hermite + maxpool2
// Grid: 512 images * 5 row-bands = 2560 blocks, 192 threads.
// Each band covers 6 pooled rows (12 conv rows, 16 input rows).
// Smem: input band 3*16*64 floats + weights 1200 + bias 16.
// ---------------------------------------------------------------------------
__global__ void conv1_fused_kernel(const float* __restrict__ x,
                                   const float* __restrict__ coef,
                                   const float* __restrict__ w,
                                   const float* __restrict__ bias) {
    extern __shared__ float smem[];
    float* s_in = smem;               // 3*16*64 = 3072
    float* s_w  = smem + 3 * 16 * 64; // 1200 (co*75 + cin*25 + ky*5 + kx)
    float* s_b  = s_w + 1200;         // 16

    const int img  = blockIdx.x / 5;
    const int band = blockIdx.x % 5;
    const int tid  = threadIdx.x;     // 192 threads

    // cooperative loads
    const float* xim = x + (size_t)img * 3 * 64 * 64;
    const int row0 = band * 12;       // first input row of this band
    for (int i = tid; i < 3 * 16 * 64; i += 192) {
        int c   = i / (16 * 64);
        int rr  = (i / 64) % 16;
        int col = i % 64;
        s_in[i] = xim[c * 4096 + (row0 + rr) * 64 + col];
    }
    for (int i = tid; i < 1200; i += 192) s_w[i] = w[i];
    if (tid < 16) s_b[tid] = bias[tid];
    __syncthreads();

    // hermite monomial coefficients
    const float c0 = __ldg(coef + 0), c1 = __ldg(coef + 1), c2 = __ldg(coef + 2),
                c3 = __ldg(coef + 3), c4 = __ldg(coef + 4);
    const float a0 = c0 - 2.0f * c2 + 12.0f * c4;
    const float a1 = 2.0f * c1 - 12.0f * c3;
    const float a2 = 4.0f * c2 - 48.0f * c4;
    const float a3 = 8.0f * c3;
    const float a4 = 16.0f * c4;

    if (tid < 180) {
        const int pyl = tid / 30;     // pooled row within band (0..5)
        const int px  = tid % 30;     // pooled col (0..29)
        const int oy  = 2 * pyl;      // conv row within band (smem-local)
        const int ox  = 2 * px;       // conv col

        #pragma unroll 1
        for (int chunk = 0; chunk < 2; chunk++) {
            float acc[8][4];
            #pragma unroll
            for (int co = 0; co < 8; co++) {
                float bv = s_b[chunk * 8 + co];
                acc[co][0] = bv; acc[co][1] = bv; acc[co][2] = bv; acc[co][3] = bv;
            }

            #pragma unroll 1
            for (int cin = 0; cin < 3; cin++) {
                const float* rowp = s_in + cin * 16 * 64 + oy * 64 + ox;
                float va[6], vb[6];
                #pragma unroll
                for (int k = 0; k < 6; k++) va[k] = rowp[k];
                rowp += 64;
                #pragma unroll
                for (int k = 0; k < 6; k++) vb[k] = rowp[k];

                const float* wp = s_w + (chunk * 8) * 75 + cin * 25;
                #pragma unroll
                for (int ky = 0; ky < 5; ky++) {
                    if (ky) {
                        #pragma unroll
                        for (int k = 0; k < 6; k++) va[k] = vb[k];
                        rowp += 64;
                        #pragma unroll
                        for (int k = 0; k < 6; k++) vb[k] = rowp[k];
                    }
                    #pragma unroll
                    for (int co = 0; co < 8; co++) {
                        #pragma unroll
                        for (int kx = 0; kx < 5; kx++) {
                            float wv = wp[co * 75 + ky * 5 + kx];
                            acc[co][0] = fmaf(va[kx],     wv, acc[co][0]);
                            acc[co][1] = fmaf(va[kx + 1], wv, acc[co][1]);
                            acc[co][2] = fmaf(vb[kx],     wv, acc[co][2]);
                            acc[co][3] = fmaf(vb[kx + 1], wv, acc[co][3]);
                        }
                    }
                }
            }

            // hermite -> maxpool -> store
            const int py = band * 6 + pyl;
            #pragma unroll
            for (int co = 0; co < 8; co++) {
                float h0 = herm4(acc[co][0], a0, a1, a2, a3, a4);
                float h1 = herm4(acc[co][1], a0, a1, a2, a3, a4);
                float h2 = herm4(acc[co][2], a0, a1, a2, a3, a4);
                float h3 = herm4(acc[co][3], a0, a1, a2, a3, a4);
                float m = fmaxf(fmaxf(h0, h1), fmaxf(h2, h3));
                g_pool1[((img * 16 + chunk * 8 + co) * 30 + py) * 30 + px] = m;
            }
        }
    }
}

// ---------------------------------------------------------------------------
// Kernel 2: conv2 + bias + hermite + maxpool2
// Grid: 512 blocks (one image), 192 threads (169 active positions).
// Smem: input 16*30*30 + weights 6400 + bias 16 = ~83 KB (dynamic).
// ---------------------------------------------------------------------------
__global__ void conv2_fused_kernel(const float* __restrict__ coef,
                                   const float* __restrict__ w,
                                   const float* __restrict__ bias) {
    extern __shared__ float smem[];
    float* s_in = smem;                // 14400
    float* s_w  = smem + 14400;        // 6400 (co*400 + cin*25 + ky*5 + kx)
    float* s_b  = s_w + 6400;          // 16

    const int img = blockIdx.x;
    const int tid = threadIdx.x;       // 192 threads

    const float* xim = g_pool1 + (size_t)img * 14400;
    for (int i = tid; i < 14400; i += 192) s_in[i] = xim[i];
    for (int i = tid; i < 6400; i += 192) s_w[i] = w[i];
    if (tid < 16) s_b[tid] = bias[tid];
    __syncthreads();

    const float c0 = __ldg(coef + 0), c1 = __ldg(coef + 1), c2 = __ldg(coef + 2),
                c3 = __ldg(coef + 3), c4 = __ldg(coef + 4);
    const float a0 = c0 - 2.0f * c2 + 12.0f * c4;
    const float a1 = 2.0f * c1 - 12.0f * c3;
    const float a2 = 4.0f * c2 - 48.0f * c4;
    const float a3 = 8.0f * c3;
    const float a4 = 16.0f * c4;

    if (tid < 169) {
        const int py = tid / 13;       // pooled row 0..12
        const int px = tid % 13;       // pooled col 0..12
        const int oy = 2 * py;         // conv row 0..24
        const int ox = 2 * px;

        #pragma unroll 1
        for (int chunk = 0; chunk < 2; chunk++) {
            float acc[8][4];
            #pragma unroll
            for (int co = 0; co < 8; co++) {
                float bv = s_b[chunk * 8 + co];
                acc[co][0] = bv; acc[co][1] = bv; acc[co][2] = bv; acc[co][3] = bv;
            }

            #pragma unroll 1
            for (int cin = 0; cin < 16; cin++) {
                const float* rowp = s_in + cin * 900 + oy * 30 + ox;
                float va[6], vb[6];
                #pragma unroll
                for (int k = 0; k < 6; k++) va[k] = rowp[k];
                rowp += 30;
                #pragma unroll
                for (int k = 0; k < 6; k++) vb[k] = rowp[k];

                const float* wp = s_w + (chunk * 8) * 400 + cin * 25;
                #pragma unroll
                for (int ky = 0; ky < 5; ky++) {
                    if (ky) {
                        #pragma unroll
                        for (int k = 0; k < 6; k++) va[k] = vb[k];
                        rowp += 30;
                        #pragma unroll
                        for (int k = 0; k < 6; k++) vb[k] = rowp[k];
                    }
                    #pragma unroll
                    for (int co = 0; co < 8; co++) {
                        #pragma unroll
                        for (int kx = 0; kx < 5; kx++) {
                            float wv = wp[co * 400 + ky * 5 + kx];
                            acc[co][0] = fmaf(va[kx],     wv, acc[co][0]);
                            acc[co][1] = fmaf(va[kx + 1], wv, acc[co][1]);
                            acc[co][2] = fmaf(vb[kx],     wv, acc[co][2]);
                            acc[co][3] = fmaf(vb[kx + 1], wv, acc[co][3]);
                        }
                    }
                }
            }

            #pragma unroll
            for (int co = 0; co < 8; co++) {
                float h0 = herm4(acc[co][0], a0, a1, a2, a3, a4);
                float h1 = herm4(acc[co][1], a0, a1, a2, a3, a4);
                float h2 = herm4(acc[co][2], a0, a1, a2, a3, a4);
                float h3 = herm4(acc[co][3], a0, a1, a2, a3, a4);
                float m = fmaxf(fmaxf(h0, h1), fmaxf(h2, h3));
                g_pool2[((img * 16 + chunk * 8 + co) * 13 + py) * 13 + px] = m;
            }
        }
    }
}

// ---------------------------------------------------------------------------
// Kernel 3: FC [512,2704] @ [2704,10]^T + bias
// Grid: 512 blocks, 128 threads.
// ---------------------------------------------------------------------------
__global__ void fc_kernel(const float* __restrict__ w,
                          const float* __restrict__ bias,
                          float* __restrict__ out) {
    const int img = blockIdx.x;
    const int tid = threadIdx.x;   // 128

    const float* xv = g_pool2 + (size_t)img * 2704;
    float p[10];
    #pragma unroll
    for (int o = 0; o < 10; o++) p[o] = 0.0f;

    for (int k = tid; k < 2704; k += 128) {
        float v = xv[k];
        #pragma unroll
        for (int o = 0; o < 10; o++) p[o] = fmaf(v, w[o * 2704 + k], p[o]);
    }

    __shared__ float red[4][10];
    const int lane = tid & 31, wrp = tid >> 5;
    #pragma unroll
    for (int o = 0; o < 10; o++) {
        float v = p[o];
        #pragma unroll
        for (int s = 16; s > 0; s >>= 1)
            v += __shfl_down_sync(0xffffffffu, v, s);
        if (lane == 0) red[wrp][o] = v;
    }
    __syncthreads();
    if (tid < 10)
        out[img * 10 + tid] =
            red[0][tid] + red[1][tid] + red[2][tid] + red[3][tid] + bias[tid];
}

// ---------------------------------------------------------------------------
extern "C" void kernel_launch(void* const* d_in, const int* in_sizes, int n_in,
                              void* d_out, int out_size) {
    const float* x       = (const float*)d_in[0];
    const float* coef    = (const float*)d_in[1];
    const float* conv1_w = (const float*)d_in[2];
    const float* conv1_b = (const float*)d_in[3];
    const float* conv2_w = (const float*)d_in[4];
    const float* conv2_b = (const float*)d_in[5];
    const float* fc1_w   = (const float*)d_in[6];
    const float* fc1_b   = (const float*)d_in[7];
    float* out = (float*)d_out;

    const int smem1 = (3 * 16 * 64 + 1200 + 16) * sizeof(float);   // ~17.2 KB
    const int smem2 = (14400 + 6400 + 16) * sizeof(float);         // ~83.3 KB

    cudaFuncSetAttribute(conv2_fused_kernel,
                         cudaFuncAttributeMaxDynamicSharedMemorySize, smem2);

    conv1_fused_kernel<<<B_IMG * 5, 192, smem1>>>(x, coef, conv1_w, conv1_b);
    conv2_fused_kernel<<<B_IMG, 192, smem2>>>(coef, conv2_w, conv2_b);
    fc_kernel<<<B_IMG, 128>>>(fc1_w, fc1_b, out);
}